// round 7
// baseline (speedup 1.0000x reference)
#include <cuda_runtime.h>
#include <math.h>

#define NR 400000
#define DD 128
#define SS 64
#define GG 256

// ---------------- scratch (device globals: no allocations allowed) ----------
__device__ float d_x1[(size_t)NR * DD];   // sub @ W1 + b1 (pre-BN)
__device__ float d_hf[(size_t)NR * DD];   // h_fused
__device__ float d_y [(size_t)NR * DD];   // [h_fused,h_dev] @ Ws1 + bs1 (pre-BN)
__device__ float d_logit[NR];
__device__ float d_e[NR];

__device__ float d_cs1[DD], d_cq1[DD], d_cs2[DD], d_cq2[DD];  // BN column stats
__device__ float d_a1[DD], d_c1[DD], d_a2[DD], d_c2[DD];      // BN affine params
__device__ float d_gsum[GG * DD], d_gsq[GG * DD];
__device__ float d_gmean[GG * DD], d_ginv[GG * DD];
__device__ float d_cnt[GG];
__device__ unsigned d_smax[GG];
__device__ float d_denom[GG];
__device__ float d_accb[GG * DD];

// ordered-uint encoding for float atomicMax
__device__ __forceinline__ unsigned f2o(float f) {
    unsigned u = __float_as_uint(f);
    return (u & 0x80000000u) ? ~u : (u | 0x80000000u);
}
__device__ __forceinline__ float o2f(unsigned u) {
    return (u & 0x80000000u) ? __uint_as_float(u & 0x7fffffffu)
                             : __uint_as_float(~u);
}

// ---------------- init ------------------------------------------------------
__global__ void init_k() {
    int i = blockIdx.x * 128 + threadIdx.x;   // grid covers GG*DD = 32768
    d_gsum[i] = 0.f; d_gsq[i] = 0.f; d_accb[i] = 0.f;
    if (i < DD) { d_cs1[i] = 0.f; d_cq1[i] = 0.f; d_cs2[i] = 0.f; d_cq2[i] = 0.f; }
    if (i < GG) { d_cnt[i] = 0.f; d_denom[i] = 0.f; d_smax[i] = 0u; }
}

// ---------------- fused tiled SGEMM: C[N,128] = A[N,K] @ W[K,128] -----------
// BM=128, BN=128 (full width), BK=16, 256 threads, 8x8 per thread.
// MODE 1: A = sub (K=64).       epilogue: store x1, accumulate BN1 stats.
// MODE 2: A = [h | relu(BN1(x1))] (K=256). epilogue: gate=sigmoid, store h_fused.
// MODE 3: A = [h_fused | h_dev(on-the-fly)] (K=256). epilogue: store y, BN2 stats.
template<int KDIM, int MODE>
__global__ __launch_bounds__(256) void gemm_k(
    const float* __restrict__ A0,        // sub (1) / h (2) / h (3)
    const float* __restrict__ W,
    const float* __restrict__ bias,
    const int*   __restrict__ batch)
{
    __shared__ float As[16][132];        // padded: conflict-free k-major stores
    __shared__ float Bs[16][128];

    const int t  = threadIdx.x;
    const int tx = t & 15, ty = t >> 4;
    const int row0 = blockIdx.x * 128;
    const int kl = t & 15, ml = t >> 4;      // A-load mapping
    const int kb = t >> 4, db = (t & 15) * 8; // B-load mapping

    int grow[8];
    if (MODE == 3) {
        #pragma unroll
        for (int i = 0; i < 8; i++) grow[i] = batch[row0 + ml + i * 16];
    }

    float acc[8][8];
    #pragma unroll
    for (int i = 0; i < 8; i++)
        #pragma unroll
        for (int j = 0; j < 8; j++) acc[i][j] = 0.f;

    for (int k0 = 0; k0 < KDIM; k0 += 16) {
        // A tile: per load-instr = 2 rows x 16 consecutive k -> 4x32B sectors
        #pragma unroll
        for (int i = 0; i < 8; i++) {
            int m = ml + i * 16;
            int row = row0 + m;
            int k = k0 + kl;
            float v;
            if (MODE == 1) {
                v = A0[(size_t)row * SS + k];
            } else if (MODE == 2) {
                if (k < DD) v = A0[(size_t)row * DD + k];
                else {
                    int kk = k - DD;
                    v = fmaxf(d_a1[kk] * d_x1[(size_t)row * DD + kk] + d_c1[kk], 0.f);
                }
            } else {
                if (k < DD) v = d_hf[(size_t)row * DD + k];
                else {
                    int kk = k - DD;
                    int g = grow[i];
                    v = (A0[(size_t)row * DD + kk] - d_gmean[g * DD + kk]) * d_ginv[g * DD + kk];
                }
            }
            As[kl][m] = v;
        }
        // B tile (weights, L2-resident after first wave)
        {
            const float4* wp = (const float4*)&W[(size_t)(k0 + kb) * DD + db];
            float4 w0 = wp[0], w1 = wp[1];
            *(float4*)&Bs[kb][db]     = w0;
            *(float4*)&Bs[kb][db + 4] = w1;
        }
        __syncthreads();
        #pragma unroll
        for (int kk = 0; kk < 16; kk++) {
            float4 a0 = *(const float4*)&As[kk][ty * 8];
            float4 a1 = *(const float4*)&As[kk][ty * 8 + 4];
            float4 b0 = *(const float4*)&Bs[kk][tx * 8];
            float4 b1 = *(const float4*)&Bs[kk][tx * 8 + 4];
            float a[8] = {a0.x, a0.y, a0.z, a0.w, a1.x, a1.y, a1.z, a1.w};
            float b[8] = {b0.x, b0.y, b0.z, b0.w, b1.x, b1.y, b1.z, b1.w};
            #pragma unroll
            for (int i = 0; i < 8; i++)
                #pragma unroll
                for (int j = 0; j < 8; j++)
                    acc[i][j] = fmaf(a[i], b[j], acc[i][j]);
        }
        __syncthreads();
    }

    const int colb = tx * 8;
    if (MODE == 1 || MODE == 3) {
        float* outp = (MODE == 1) ? d_x1 : d_y;
        float cs[8], cq[8];
        #pragma unroll
        for (int j = 0; j < 8; j++) { cs[j] = 0.f; cq[j] = 0.f; }
        #pragma unroll
        for (int i = 0; i < 8; i++) {
            int row = row0 + ty * 8 + i;
            float v[8];
            #pragma unroll
            for (int j = 0; j < 8; j++) {
                v[j] = acc[i][j] + bias[colb + j];
                cs[j] += v[j];
                cq[j] += v[j] * v[j];
            }
            float4* op = (float4*)&outp[(size_t)row * DD + colb];
            op[0] = make_float4(v[0], v[1], v[2], v[3]);
            op[1] = make_float4(v[4], v[5], v[6], v[7]);
        }
        // block-level column reduction, then one atomic per column
        float* csum = (MODE == 1) ? d_cs1 : d_cs2;
        float* csq  = (MODE == 1) ? d_cq1 : d_cq2;
        float* red = &As[0][0];  // reuse smem (>=2048 floats)
        __syncthreads();
        #pragma unroll
        for (int j = 0; j < 8; j++) red[ty * 128 + colb + j] = cs[j];
        __syncthreads();
        if (t < 128) {
            float s = 0.f;
            #pragma unroll
            for (int r = 0; r < 16; r++) s += red[r * 128 + t];
            atomicAdd(&csum[t], s);
        }
        __syncthreads();
        #pragma unroll
        for (int j = 0; j < 8; j++) red[ty * 128 + colb + j] = cq[j];
        __syncthreads();
        if (t < 128) {
            float s = 0.f;
            #pragma unroll
            for (int r = 0; r < 16; r++) s += red[r * 128 + t];
            atomicAdd(&csq[t], s);
        }
    } else {  // MODE 2: gate + h_fused
        #pragma unroll
        for (int i = 0; i < 8; i++) {
            int row = row0 + ty * 8 + i;
            const float4* hp = (const float4*)&A0  [(size_t)row * DD + colb];
            const float4* xp = (const float4*)&d_x1[(size_t)row * DD + colb];
            float4 h0 = hp[0], h1 = hp[1], x0 = xp[0], x1v = xp[1];
            float hv[8] = {h0.x, h0.y, h0.z, h0.w, h1.x, h1.y, h1.z, h1.w};
            float xv[8] = {x0.x, x0.y, x0.z, x0.w, x1v.x, x1v.y, x1v.z, x1v.w};
            float o[8];
            #pragma unroll
            for (int j = 0; j < 8; j++) {
                int col = colb + j;
                float se   = fmaxf(d_a1[col] * xv[j] + d_c1[col], 0.f);
                float gate = 1.f / (1.f + expf(-(acc[i][j] + bias[col])));
                o[j] = hv[j] + gate * se;
            }
            float4* op = (float4*)&d_hf[(size_t)row * DD + colb];
            op[0] = make_float4(o[0], o[1], o[2], o[3]);
            op[1] = make_float4(o[4], o[5], o[6], o[7]);
        }
    }
}

// ---------------- per-graph sum / sumsq of h (sorted segments) --------------
__global__ void seg_stats_h(const float* __restrict__ h, const int* __restrict__ batch)
{
    __shared__ int sb[128];
    int d = threadIdx.x;
    int r0 = blockIdx.x * 128;   // NR/128 = 3125 blocks, exact
    sb[d] = batch[r0 + d];
    __syncthreads();
    float s = 0.f, q = 0.f, c = 0.f;
    int cur = sb[0];
    for (int i = 0; i < 128; i++) {
        int g = sb[i];
        if (g != cur) {
            atomicAdd(&d_gsum[cur * DD + d], s);
            atomicAdd(&d_gsq [cur * DD + d], q);
            if (d == 0) atomicAdd(&d_cnt[cur], c);
            s = 0.f; q = 0.f; c = 0.f; cur = g;
        }
        float v = h[(size_t)(r0 + i) * DD + d];
        s += v; q += v * v; c += 1.f;
    }
    atomicAdd(&d_gsum[cur * DD + d], s);
    atomicAdd(&d_gsq [cur * DD + d], q);
    if (d == 0) atomicAdd(&d_cnt[cur], c);
}

// ---------------- finalize BN1 + graph mean/inv-std -------------------------
__global__ void finalize1(const float* __restrict__ g1, const float* __restrict__ be1)
{
    int g = blockIdx.x, d = threadIdx.x;
    float cnt = fmaxf(d_cnt[g], 1.f);
    float m  = d_gsum[g * DD + d] / cnt;
    float sq = d_gsq [g * DD + d] / cnt;
    float sd = sqrtf(fmaxf(sq - m * m, 1e-8f));
    d_gmean[g * DD + d] = m;
    d_ginv [g * DD + d] = 1.f / (sd + 1e-8f);
    if (g == 0) {
        float mean = d_cs1[d] / (float)NR;
        float var  = d_cq1[d] / (float)NR - mean * mean;
        float a = g1[d] * rsqrtf(var + 1e-5f);
        d_a1[d] = a;
        d_c1[d] = be1[d] - mean * a;
    }
}

__global__ void finalize2(const float* __restrict__ g2, const float* __restrict__ be2)
{
    int d = threadIdx.x;
    float mean = d_cs2[d] / (float)NR;
    float var  = d_cq2[d] / (float)NR - mean * mean;
    float a = g2[d] * rsqrtf(var + 1e-5f);
    d_a2[d] = a;
    d_c2[d] = be2[d] - mean * a;
}

// ---------------- score logit: warp per row ---------------------------------
__global__ void logit_k(const float* __restrict__ Ws2, const float* __restrict__ bs2,
                        const int* __restrict__ batch)
{
    int w = threadIdx.x >> 5, l = threadIdx.x & 31;
    int row = blockIdx.x * 8 + w;   // NR/8 = 50000 blocks, exact
    float p = 0.f;
    #pragma unroll
    for (int c = 0; c < 4; c++) {
        int col = c * 32 + l;
        float z = fmaxf(d_a2[col] * d_y[(size_t)row * DD + col] + d_c2[col], 0.f);
        p = fmaf(z, Ws2[col], p);
    }
    #pragma unroll
    for (int o = 16; o; o >>= 1) p += __shfl_down_sync(0xffffffffu, p, o);
    if (l == 0) {
        float lg = p + bs2[0];
        d_logit[row] = lg;
        atomicMax(&d_smax[batch[row]], f2o(lg));
    }
}

// ---------------- exp + segment denom ---------------------------------------
__global__ void exp_k(const int* __restrict__ batch)
{
    int r = blockIdx.x * 256 + threadIdx.x;
    if (r >= NR) return;
    int g = batch[r];
    float mx = o2f(d_smax[g]);
    float e = expf(d_logit[r] - mx);
    d_e[r] = e;
    atomicAdd(&d_denom[g], e);
}

// ---------------- weighted segment sum of h_fused * score -------------------
__global__ void wsum_k(const int* __restrict__ batch)
{
    __shared__ int   sb[256];
    __shared__ float ss[256];
    int d = threadIdx.x;      // 128 threads, one column each
    int r0 = blockIdx.x * 256;
    for (int i = d; i < 256; i += 128) {
        int r = r0 + i;
        if (r < NR) {
            int g = batch[r];
            sb[i] = g;
            ss[i] = d_e[r] / d_denom[g];
        } else sb[i] = -1;
    }
    __syncthreads();
    float a = 0.f;
    int cur = sb[0];
    for (int i = 0; i < 256; i++) {
        int g = sb[i];
        if (g < 0) break;
        if (g != cur) {
            atomicAdd(&d_accb[cur * DD + d], a);
            a = 0.f; cur = g;
        }
        a = fmaf(d_hf[(size_t)(r0 + i) * DD + d], ss[i], a);
    }
    atomicAdd(&d_accb[cur * DD + d], a);
}

// ---------------- final mix --------------------------------------------------
__global__ void final_k(const float* __restrict__ mix, float* __restrict__ out)
{
    int g = blockIdx.x, d = threadIdx.x;
    float alpha = 1.f / (1.f + expf(-mix[0]));
    out[g * DD + d] = alpha * d_accb[g * DD + d] + (1.f - alpha) * d_gmean[g * DD + d];
}

// ---------------- launch ------------------------------------------------------
extern "C" void kernel_launch(void* const* d_in, const int* in_sizes, int n_in,
                              void* d_out, int out_size)
{
    const float* h     = (const float*)d_in[0];
    const float* sub   = (const float*)d_in[1];
    const int*   batch = (const int*)  d_in[2];
    const float* W1    = (const float*)d_in[3];
    const float* b1    = (const float*)d_in[4];
    const float* g1    = (const float*)d_in[5];
    const float* be1   = (const float*)d_in[6];
    const float* Wg    = (const float*)d_in[7];
    const float* bg    = (const float*)d_in[8];
    const float* Ws1   = (const float*)d_in[9];
    const float* bs1   = (const float*)d_in[10];
    const float* g2    = (const float*)d_in[11];
    const float* be2   = (const float*)d_in[12];
    const float* Ws2   = (const float*)d_in[13];
    const float* bs2   = (const float*)d_in[14];
    const float* mix   = (const float*)d_in[15];
    float* out = (float*)d_out;

    init_k<<<GG * DD / 128, 128>>>();
    gemm_k<SS, 1><<<NR / 128, 256>>>(sub, W1, b1, batch);      // x1 + BN1 stats
    seg_stats_h<<<NR / 128, 128>>>(h, batch);                  // graph sums of h
    finalize1<<<GG, 128>>>(g1, be1);                           // BN1 affine + graph mean/std
    gemm_k<2 * DD, 2><<<NR / 128, 256>>>(h, Wg, bg, batch);    // gate -> h_fused
    gemm_k<2 * DD, 3><<<NR / 128, 256>>>(h, Ws1, bs1, batch);  // y + BN2 stats
    finalize2<<<1, 128>>>(g2, be2);                            // BN2 affine
    logit_k<<<NR / 8, 256>>>(Ws2, bs2, batch);                 // logits + segment max
    exp_k<<<(NR + 255) / 256, 256>>>(batch);                   // exp + segment denom
    wsum_k<<<(NR + 255) / 256, 128>>>(batch);                  // weighted segment sum
    final_k<<<GG, 128>>>(mix, out);                            // alpha mix
}

// round 9
// speedup vs baseline: 1.6811x; 1.6811x over previous
#include <cuda_runtime.h>
#include <math.h>
#include <stdint.h>

#define NR 400000
#define DD 128
#define GG 256

// ---------------- scratch (device globals: no allocations allowed) ----------
__device__ float d_x1[(size_t)NR * DD];   // sub @ W1 + b1 (pre-BN)
__device__ float d_hf[(size_t)NR * DD];   // h_fused
__device__ float d_y [(size_t)NR * DD];   // [h_fused,h_dev] @ Ws1 + bs1 (pre-BN)
__device__ float d_logit[NR];
__device__ float d_e[NR];

__device__ float d_cs1[DD], d_cq1[DD], d_cs2[DD], d_cq2[DD];  // BN column stats
__device__ float d_a1[DD], d_c1[DD], d_a2[DD], d_c2[DD];      // BN affine params
__device__ float d_gsum[GG * DD], d_gsq[GG * DD];
__device__ float d_gmean[GG * DD], d_ginv[GG * DD];
__device__ float d_cnt[GG];
__device__ unsigned d_smax[GG];
__device__ float d_denom[GG];
__device__ float d_accb[GG * DD];

// ordered-uint encoding for float atomicMax
__device__ __forceinline__ unsigned f2o(float f) {
    unsigned u = __float_as_uint(f);
    return (u & 0x80000000u) ? ~u : (u | 0x80000000u);
}
__device__ __forceinline__ float o2f(unsigned u) {
    return (u & 0x80000000u) ? __uint_as_float(u & 0x7fffffffu)
                             : __uint_as_float(~u);
}

__device__ __forceinline__ uint32_t tf32c(float f) {
    uint32_t u;
    asm("cvt.rna.tf32.f32 %0, %1;" : "=r"(u) : "f"(f));
    return u;
}

__device__ __forceinline__ void mma8(float* c, const uint32_t* a, const uint32_t* b) {
    asm volatile(
        "mma.sync.aligned.m16n8k8.row.col.f32.tf32.tf32.f32 "
        "{%0,%1,%2,%3}, {%4,%5,%6,%7}, {%8,%9}, {%0,%1,%2,%3};"
        : "+f"(c[0]), "+f"(c[1]), "+f"(c[2]), "+f"(c[3])
        : "r"(a[0]), "r"(a[1]), "r"(a[2]), "r"(a[3]), "r"(b[0]), "r"(b[1]));
}

// ---------------- init ------------------------------------------------------
__global__ void init_k() {
    int i = blockIdx.x * 128 + threadIdx.x;   // grid covers GG*DD = 32768
    d_gsum[i] = 0.f; d_gsq[i] = 0.f; d_accb[i] = 0.f;
    if (i < DD) { d_cs1[i] = 0.f; d_cq1[i] = 0.f; d_cs2[i] = 0.f; d_cq2[i] = 0.f; }
    if (i < GG) { d_cnt[i] = 0.f; d_denom[i] = 0.f; d_smax[i] = 0u; }
}

// ---------------- tf32 mma.sync fused GEMM: C[128,128] per CTA --------------
// BM=128, BN=128, BK=32, 256 thr = 8 warps (4x2), warp = 32x64 (2x8 m16n8k8).
// MODE 1: A = sub (K=64).                  epi: store x1, BN1 column stats.
// MODE 2: A = [h | relu(BN1(x1))] (K=256). epi: sigmoid gate -> h_fused.
// MODE 3: A = [h_fused | h_dev] (K=256).   epi: store y, BN2 column stats.
#define KST 136   // smem k-row stride (floats): fragment loads conflict-free
template<int NCHUNK, int MODE>
__global__ __launch_bounds__(256) void mma_gemm(
    const float* __restrict__ A0,        // sub (1) / h (2) / h (3)
    const float* __restrict__ W,         // [K,128] row-major
    const float* __restrict__ bias,
    const int*   __restrict__ batch)
{
    __shared__ uint32_t As[32 * KST];
    __shared__ uint32_t Bs[32 * KST];
    __shared__ float sbias[DD], sa1[DD], sc1[DD];

    const int t = threadIdx.x;
    const int lane = t & 31;
    const int wid  = t >> 5;
    const int warp_m = wid & 3;          // 4 row tiles of 32
    const int warp_n = wid >> 2;         // 2 col tiles of 64
    const int lr = lane >> 2, lc = lane & 3;
    const int row0 = blockIdx.x * 128;

    // producer mapping: row = t&127, k-half = t>>7 (16 k each)
    const int prow = t & 127;
    const int kh   = (t >> 7) * 16;
    const int grow = row0 + prow;

    if (t < DD) {
        sbias[t] = bias[t];
        if (MODE == 2) { sa1[t] = d_a1[t]; sc1[t] = d_c1[t]; }
    }
    int g3 = 0;
    if (MODE == 3) g3 = batch[grow];

    float acc[2][8][4];
    #pragma unroll
    for (int i = 0; i < 2; i++)
        #pragma unroll
        for (int j = 0; j < 8; j++)
            #pragma unroll
            for (int e = 0; e < 4; e++) acc[i][j][e] = 0.f;

    for (int c = 0; c < NCHUNK; c++) {
        const int kg = c * 32;
        // ---- A chunk: 16 floats for (prow, kg+kh .. +15) ----
        float4 va[4];
        if (MODE == 1) {
            const float4* p = (const float4*)(A0 + (size_t)grow * 64 + kg + kh);
            #pragma unroll
            for (int i = 0; i < 4; i++) va[i] = p[i];
        } else if (MODE == 2) {
            if (c < 4) {
                const float4* p = (const float4*)(A0 + (size_t)grow * DD + kg + kh);
                #pragma unroll
                for (int i = 0; i < 4; i++) va[i] = p[i];
            } else {
                const int kk = kg - DD + kh;
                const float4* p = (const float4*)(d_x1 + (size_t)grow * DD + kk);
                #pragma unroll
                for (int i = 0; i < 4; i++) {
                    float4 x = p[i];
                    va[i].x = fmaxf(sa1[kk+i*4+0] * x.x + sc1[kk+i*4+0], 0.f);
                    va[i].y = fmaxf(sa1[kk+i*4+1] * x.y + sc1[kk+i*4+1], 0.f);
                    va[i].z = fmaxf(sa1[kk+i*4+2] * x.z + sc1[kk+i*4+2], 0.f);
                    va[i].w = fmaxf(sa1[kk+i*4+3] * x.w + sc1[kk+i*4+3], 0.f);
                }
            }
        } else {
            if (c < 4) {
                const float4* p = (const float4*)(d_hf + (size_t)grow * DD + kg + kh);
                #pragma unroll
                for (int i = 0; i < 4; i++) va[i] = p[i];
            } else {
                const int kk = kg - DD + kh;
                const float4* hp = (const float4*)(A0      + (size_t)grow * DD + kk);
                const float4* mp = (const float4*)(d_gmean + (size_t)g3   * DD + kk);
                const float4* ip = (const float4*)(d_ginv  + (size_t)g3   * DD + kk);
                #pragma unroll
                for (int i = 0; i < 4; i++) {
                    float4 h4 = hp[i], m4 = mp[i], i4 = ip[i];
                    va[i].x = (h4.x - m4.x) * i4.x;
                    va[i].y = (h4.y - m4.y) * i4.y;
                    va[i].z = (h4.z - m4.z) * i4.z;
                    va[i].w = (h4.w - m4.w) * i4.w;
                }
            }
        }
        if (c > 0) __syncthreads();   // ensure prev chunk fully consumed
        {
            const float* vf = (const float*)va;
            #pragma unroll
            for (int ii = 0; ii < 16; ii++)
                As[(kh + ii) * KST + prow] = tf32c(vf[ii]);
        }
        // ---- B chunk: W[kg+k][col] -> Bs[k][col], 16 floats/thread ----
        {
            const int bk = t >> 3, bc = (t & 7) * 16;
            const float4* wp = (const float4*)(W + (size_t)(kg + bk) * DD + bc);
            #pragma unroll
            for (int i = 0; i < 4; i++) {
                float4 w4 = wp[i];
                uint32_t* bd = &Bs[bk * KST + bc + i * 4];
                bd[0] = tf32c(w4.x); bd[1] = tf32c(w4.y);
                bd[2] = tf32c(w4.z); bd[3] = tf32c(w4.w);
            }
        }
        __syncthreads();

        // ---- 4 k-steps of m16n8k8 ----
        #pragma unroll
        for (int ks = 0; ks < 4; ks++) {
            const int k0 = ks * 8;
            uint32_t af[2][4];
            {
                const uint32_t* a0 = &As[(k0 + lc) * KST + warp_m * 32 + lr];
                const uint32_t* a4 = a0 + 4 * KST;
                #pragma unroll
                for (int i = 0; i < 2; i++) {
                    af[i][0] = a0[i * 16];
                    af[i][1] = a0[i * 16 + 8];
                    af[i][2] = a4[i * 16];
                    af[i][3] = a4[i * 16 + 8];
                }
            }
            const uint32_t* b0 = &Bs[(k0 + lc) * KST + warp_n * 64 + lr];
            const uint32_t* b4 = b0 + 4 * KST;
            #pragma unroll
            for (int j = 0; j < 8; j++) {
                uint32_t bf[2] = { b0[j * 8], b4[j * 8] };
                mma8(acc[0][j], af[0], bf);
                mma8(acc[1][j], af[1], bf);
            }
        }
    }
    __syncthreads();

    // ---- epilogue ----
    // thread owns rows: row0 + warp_m*32 + i*16 + lr + h*8  (i,h in 0..1)
    // cols: warp_n*64 + j*8 + lc*2 + {0,1}
    if (MODE == 1 || MODE == 3) {
        float* outp = (MODE == 1) ? d_x1 : d_y;
        float* gcs = (MODE == 1) ? d_cs1 : d_cs2;
        float* gcq = (MODE == 1) ? d_cq1 : d_cq2;
        float cs[8][2], cq[8][2];
        #pragma unroll
        for (int j = 0; j < 8; j++)
            #pragma unroll
            for (int e = 0; e < 2; e++) { cs[j][e] = 0.f; cq[j][e] = 0.f; }
        #pragma unroll
        for (int i = 0; i < 2; i++) {
            #pragma unroll
            for (int hh = 0; hh < 2; hh++) {
                int row = row0 + warp_m * 32 + i * 16 + lr + hh * 8;
                float* op = outp + (size_t)row * DD;
                #pragma unroll
                for (int j = 0; j < 8; j++) {
                    int col = warp_n * 64 + j * 8 + lc * 2;
                    float v0 = acc[i][j][hh * 2 + 0] + sbias[col];
                    float v1 = acc[i][j][hh * 2 + 1] + sbias[col + 1];
                    *(float2*)(op + col) = make_float2(v0, v1);
                    cs[j][0] += v0; cq[j][0] += v0 * v0;
                    cs[j][1] += v1; cq[j][1] += v1 * v1;
                }
            }
        }
        // reduce over the 8 row-lanes (stride-4 lanes share columns)
        #pragma unroll
        for (int o = 4; o < 32; o <<= 1) {
            #pragma unroll
            for (int j = 0; j < 8; j++)
                #pragma unroll
                for (int e = 0; e < 2; e++) {
                    cs[j][e] += __shfl_xor_sync(0xffffffffu, cs[j][e], o);
                    cq[j][e] += __shfl_xor_sync(0xffffffffu, cq[j][e], o);
                }
        }
        if (lr == 0) {
            #pragma unroll
            for (int j = 0; j < 8; j++) {
                int col = warp_n * 64 + j * 8 + lc * 2;
                atomicAdd(&gcs[col],     cs[j][0]);
                atomicAdd(&gcs[col + 1], cs[j][1]);
                atomicAdd(&gcq[col],     cq[j][0]);
                atomicAdd(&gcq[col + 1], cq[j][1]);
            }
        }
    } else {  // MODE 2: gate sigmoid -> h_fused
        #pragma unroll
        for (int i = 0; i < 2; i++) {
            #pragma unroll
            for (int hh = 0; hh < 2; hh++) {
                int row = row0 + warp_m * 32 + i * 16 + lr + hh * 8;
                const float* hp = A0   + (size_t)row * DD;
                const float* xp = d_x1 + (size_t)row * DD;
                float* op = d_hf + (size_t)row * DD;
                #pragma unroll
                for (int j = 0; j < 8; j++) {
                    int col = warp_n * 64 + j * 8 + lc * 2;
                    float2 h2 = *(const float2*)(hp + col);
                    float2 x2 = *(const float2*)(xp + col);
                    float se0 = fmaxf(sa1[col]   * x2.x + sc1[col],   0.f);
                    float se1 = fmaxf(sa1[col+1] * x2.y + sc1[col+1], 0.f);
                    float a0v = acc[i][j][hh * 2 + 0] + sbias[col];
                    float a1v = acc[i][j][hh * 2 + 1] + sbias[col + 1];
                    float g0 = 1.f / (1.f + expf(-a0v));
                    float g1 = 1.f / (1.f + expf(-a1v));
                    *(float2*)(op + col) =
                        make_float2(h2.x + g0 * se0, h2.y + g1 * se1);
                }
            }
        }
    }
}

// ---------------- per-graph sum / sumsq of h (sorted segments) --------------
__global__ void seg_stats_h(const float* __restrict__ h, const int* __restrict__ batch)
{
    __shared__ int sb[128];
    int d = threadIdx.x;
    int r0 = blockIdx.x * 128;
    sb[d] = batch[r0 + d];
    __syncthreads();
    float s = 0.f, q = 0.f, c = 0.f;
    int cur = sb[0];
    for (int i = 0; i < 128; i++) {
        int g = sb[i];
        if (g != cur) {
            atomicAdd(&d_gsum[cur * DD + d], s);
            atomicAdd(&d_gsq [cur * DD + d], q);
            if (d == 0) atomicAdd(&d_cnt[cur], c);
            s = 0.f; q = 0.f; c = 0.f; cur = g;
        }
        float v = h[(size_t)(r0 + i) * DD + d];
        s += v; q += v * v; c += 1.f;
    }
    atomicAdd(&d_gsum[cur * DD + d], s);
    atomicAdd(&d_gsq [cur * DD + d], q);
    if (d == 0) atomicAdd(&d_cnt[cur], c);
}

// ---------------- finalize BN1 + graph mean/inv-std -------------------------
__global__ void finalize1(const float* __restrict__ g1, const float* __restrict__ be1)
{
    int g = blockIdx.x, d = threadIdx.x;
    float cnt = fmaxf(d_cnt[g], 1.f);
    float m  = d_gsum[g * DD + d] / cnt;
    float sq = d_gsq [g * DD + d] / cnt;
    float sd = sqrtf(fmaxf(sq - m * m, 1e-8f));
    d_gmean[g * DD + d] = m;
    d_ginv [g * DD + d] = 1.f / (sd + 1e-8f);
    if (g == 0) {
        float mean = d_cs1[d] / (float)NR;
        float var  = d_cq1[d] / (float)NR - mean * mean;
        float a = g1[d] * rsqrtf(var + 1e-5f);
        d_a1[d] = a;
        d_c1[d] = be1[d] - mean * a;
    }
}

__global__ void finalize2(const float* __restrict__ g2, const float* __restrict__ be2)
{
    int d = threadIdx.x;
    float mean = d_cs2[d] / (float)NR;
    float var  = d_cq2[d] / (float)NR - mean * mean;
    float a = g2[d] * rsqrtf(var + 1e-5f);
    d_a2[d] = a;
    d_c2[d] = be2[d] - mean * a;
}

// ---------------- score logit: warp per row ---------------------------------
__global__ void logit_k(const float* __restrict__ Ws2, const float* __restrict__ bs2,
                        const int* __restrict__ batch)
{
    int w = threadIdx.x >> 5, l = threadIdx.x & 31;
    int row = blockIdx.x * 8 + w;
    float p = 0.f;
    #pragma unroll
    for (int c = 0; c < 4; c++) {
        int col = c * 32 + l;
        float z = fmaxf(d_a2[col] * d_y[(size_t)row * DD + col] + d_c2[col], 0.f);
        p = fmaf(z, Ws2[col], p);
    }
    #pragma unroll
    for (int o = 16; o; o >>= 1) p += __shfl_down_sync(0xffffffffu, p, o);
    if (l == 0) {
        float lg = p + bs2[0];
        d_logit[row] = lg;
        atomicMax(&d_smax[batch[row]], f2o(lg));
    }
}

// ---------------- exp + segment denom ---------------------------------------
__global__ void exp_k(const int* __restrict__ batch)
{
    int r = blockIdx.x * 256 + threadIdx.x;
    if (r >= NR) return;
    int g = batch[r];
    float mx = o2f(d_smax[g]);
    float e = expf(d_logit[r] - mx);
    d_e[r] = e;
    atomicAdd(&d_denom[g], e);
}

// ---------------- weighted segment sum of h_fused * score -------------------
__global__ void wsum_k(const int* __restrict__ batch)
{
    __shared__ int   sb[256];
    __shared__ float ss[256];
    int d = threadIdx.x;
    int r0 = blockIdx.x * 256;
    for (int i = d; i < 256; i += 128) {
        int r = r0 + i;
        if (r < NR) {
            int g = batch[r];
            sb[i] = g;
            ss[i] = d_e[r] / d_denom[g];
        } else sb[i] = -1;
    }
    __syncthreads();
    float a = 0.f;
    int cur = sb[0];
    for (int i = 0; i < 256; i++) {
        int g = sb[i];
        if (g < 0) break;
        if (g != cur) {
            atomicAdd(&d_accb[cur * DD + d], a);
            a = 0.f; cur = g;
        }
        a = fmaf(d_hf[(size_t)(r0 + i) * DD + d], ss[i], a);
    }
    atomicAdd(&d_accb[cur * DD + d], a);
}

// ---------------- final mix --------------------------------------------------
__global__ void final_k(const float* __restrict__ mix, float* __restrict__ out)
{
    int g = blockIdx.x, d = threadIdx.x;
    float alpha = 1.f / (1.f + expf(-mix[0]));
    out[g * DD + d] = alpha * d_accb[g * DD + d] + (1.f - alpha) * d_gmean[g * DD + d];
}

// ---------------- launch ------------------------------------------------------
extern "C" void kernel_launch(void* const* d_in, const int* in_sizes, int n_in,
                              void* d_out, int out_size)
{
    const float* h     = (const float*)d_in[0];
    const float* sub   = (const float*)d_in[1];
    const int*   batch = (const int*)  d_in[2];
    const float* W1    = (const float*)d_in[3];
    const float* b1    = (const float*)d_in[4];
    const float* g1    = (const float*)d_in[5];
    const float* be1   = (const float*)d_in[6];
    const float* Wg    = (const float*)d_in[7];
    const float* bg    = (const float*)d_in[8];
    const float* Ws1   = (const float*)d_in[9];
    const float* bs1   = (const float*)d_in[10];
    const float* g2    = (const float*)d_in[11];
    const float* be2   = (const float*)d_in[12];
    const float* Ws2   = (const float*)d_in[13];
    const float* bs2   = (const float*)d_in[14];
    const float* mix   = (const float*)d_in[15];
    float* out = (float*)d_out;

    init_k<<<GG * DD / 128, 128>>>();
    mma_gemm<2, 1><<<NR / 128, 256>>>(sub, W1, b1, batch);    // x1 + BN1 stats
    seg_stats_h<<<NR / 128, 128>>>(h, batch);                 // graph sums of h
    finalize1<<<GG, 128>>>(g1, be1);                          // BN1 affine + graph stats
    mma_gemm<8, 2><<<NR / 128, 256>>>(h, Wg, bg, batch);      // gate -> h_fused
    mma_gemm<8, 3><<<NR / 128, 256>>>(h, Ws1, bs1, batch);    // y + BN2 stats
    finalize2<<<1, 128>>>(g2, be2);                           // BN2 affine
    logit_k<<<NR / 8, 256>>>(Ws2, bs2, batch);                // logits + segment max
    exp_k<<<(NR + 255) / 256, 256>>>(batch);                  // exp + segment denom
    wsum_k<<<(NR + 255) / 256, 128>>>(batch);                 // weighted segment sum
    final_k<<<GG, 128>>>(mix, out);                           // alpha mix
}

// round 13
// speedup vs baseline: 1.8099x; 1.0766x over previous
#include <cuda_runtime.h>
#include <math.h>
#include <stdint.h>

#define NR 400000
#define DD 128
#define GG 256

// ---------------- scratch (device globals: no allocations allowed) ----------
__device__ float d_x1[(size_t)NR * DD];   // sub @ W1 + b1 (pre-BN)
__device__ float d_hf[(size_t)NR * DD];   // h_fused
__device__ float d_y [(size_t)NR * DD];   // [h_fused,h_dev] @ Ws1 + bs1 (pre-BN)
__device__ float d_logit[NR];
__device__ float d_e[NR];

__device__ float d_cs1[DD], d_cq1[DD], d_cs2[DD], d_cq2[DD];  // BN column stats
__device__ float d_a1[DD], d_c1[DD], d_a2[DD], d_c2[DD];      // BN affine params
__device__ float d_gsum[GG * DD], d_gsq[GG * DD];
__device__ float d_gmean[GG * DD], d_ginv[GG * DD];
__device__ float d_cnt[GG];
__device__ unsigned d_smax[GG];
__device__ float d_denom[GG];
__device__ float d_accb[GG * DD];

// ordered-uint encoding for float atomicMax
__device__ __forceinline__ unsigned f2o(float f) {
    unsigned u = __float_as_uint(f);
    return (u & 0x80000000u) ? ~u : (u | 0x80000000u);
}
__device__ __forceinline__ float o2f(unsigned u) {
    return (u & 0x80000000u) ? __uint_as_float(u & 0x7fffffffu)
                             : __uint_as_float(~u);
}

__device__ __forceinline__ void mma8(float* c, const uint32_t* a, const uint32_t* b) {
    asm volatile(
        "mma.sync.aligned.m16n8k8.row.col.f32.tf32.tf32.f32 "
        "{%0,%1,%2,%3}, {%4,%5,%6,%7}, {%8,%9}, {%0,%1,%2,%3};"
        : "+f"(c[0]), "+f"(c[1]), "+f"(c[2]), "+f"(c[3])
        : "r"(a[0]), "r"(a[1]), "r"(a[2]), "r"(a[3]), "r"(b[0]), "r"(b[1]));
}

// ---------------- init ------------------------------------------------------
__global__ void init_k() {
    int i = blockIdx.x * 128 + threadIdx.x;   // grid covers GG*DD = 32768
    d_gsum[i] = 0.f; d_gsq[i] = 0.f; d_accb[i] = 0.f;
    if (i < DD) { d_cs1[i] = 0.f; d_cq1[i] = 0.f; d_cs2[i] = 0.f; d_cq2[i] = 0.f; }
    if (i < GG) { d_cnt[i] = 0.f; d_denom[i] = 0.f; d_smax[i] = 0u; }
}

// ---------------- tf32 mma.sync fused GEMM (software-pipelined) -------------
// BM=128, BN=128, BK=32, 256 thr = 8 warps (4x2), warp = 32x64 (2x8 m16n8k8).
// Double-buffered smem; B via cp.async.cg; A prefetched 1 chunk ahead in regs.
// MODE 1: A = sub (K=64).                  epi: x1 + BN1 stats + fused seg-stats(h).
// MODE 2: A = [h | relu(BN1(x1))] (K=256). epi: sigmoid gate -> h_fused.
// MODE 3: A = [h_fused | h_dev] (K=256).   epi: store y, BN2 column stats.
#define KST 136   // smem k-row stride (floats): fragment access conflict-free
#define STG (32 * KST)
#define SMEMSZ ((4 * STG) * 4 + 2048)

template<int NCHUNK, int MODE>
__global__ __launch_bounds__(256) void mma_gemm(
    const float* __restrict__ A0,        // sub (1) / h (2) / h (3)
    const float* __restrict__ W,         // [K,128] row-major
    const float* __restrict__ bias,
    const int*   __restrict__ batch,
    const float* __restrict__ hs)        // h (used by MODE 1 seg-stats)
{
    extern __shared__ __align__(16) uint32_t dyn[];
    uint32_t* AsB = dyn;                 // 2 stages of 32*KST
    uint32_t* BsB = dyn + 2 * STG;       // 2 stages of 32*KST
    float* sbias = (float*)(dyn + 4 * STG);
    float* sa1 = sbias + 128;
    float* sc1 = sa1 + 128;
    int*   sbt = (int*)(sc1 + 128);

    const int t = threadIdx.x;
    const int lane = t & 31;
    const int wid  = t >> 5;
    const int warp_m = wid & 3;
    const int warp_n = wid >> 2;
    const int lr = lane >> 2, lc = lane & 3;
    const int row0 = blockIdx.x * 128;

    const int prow = t & 127;
    const int kh   = (t >> 7) * 16;
    const int grow = row0 + prow;

    if (t < DD) {
        sbias[t] = bias[t];
        if (MODE == 2) { sa1[t] = d_a1[t]; sc1[t] = d_c1[t]; }
    }
    int g3 = 0;
    if (MODE == 3) g3 = batch[grow];

    float acc[2][8][4];
    #pragma unroll
    for (int i = 0; i < 2; i++)
        #pragma unroll
        for (int j = 0; j < 8; j++)
            #pragma unroll
            for (int e = 0; e < 4; e++) acc[i][j][e] = 0.f;

    // ---- helpers ----
    auto cpB = [&](int c, int s) {
        uint32_t base = (uint32_t)__cvta_generic_to_shared(BsB + s * STG);
        #pragma unroll
        for (int i = 0; i < 4; i++) {
            int p = t + i * 256;
            int krow = p >> 5, pc = p & 31;
            uint32_t sa = base + (uint32_t)(krow * (KST * 4) + pc * 16);
            const float* ga = W + (size_t)(c * 32 + krow) * DD + pc * 4;
            asm volatile("cp.async.cg.shared.global [%0], [%1], 16;"
                         :: "r"(sa), "l"(ga));
        }
        asm volatile("cp.async.commit_group;" ::: "memory");
    };
    auto loadA = [&](int c, float4* va) {
        const int kg = c * 32;
        if (MODE == 1) {
            const float4* p = (const float4*)(A0 + (size_t)grow * 64 + kg + kh);
            #pragma unroll
            for (int i = 0; i < 4; i++) va[i] = p[i];
        } else if (MODE == 2) {
            if (c < 4) {
                const float4* p = (const float4*)(A0 + (size_t)grow * DD + kg + kh);
                #pragma unroll
                for (int i = 0; i < 4; i++) va[i] = p[i];
            } else {
                const int kk = kg - DD + kh;
                const float4* p = (const float4*)(d_x1 + (size_t)grow * DD + kk);
                #pragma unroll
                for (int i = 0; i < 4; i++) {
                    float4 x = p[i];
                    va[i].x = fmaxf(sa1[kk+i*4+0] * x.x + sc1[kk+i*4+0], 0.f);
                    va[i].y = fmaxf(sa1[kk+i*4+1] * x.y + sc1[kk+i*4+1], 0.f);
                    va[i].z = fmaxf(sa1[kk+i*4+2] * x.z + sc1[kk+i*4+2], 0.f);
                    va[i].w = fmaxf(sa1[kk+i*4+3] * x.w + sc1[kk+i*4+3], 0.f);
                }
            }
        } else {
            if (c < 4) {
                const float4* p = (const float4*)(d_hf + (size_t)grow * DD + kg + kh);
                #pragma unroll
                for (int i = 0; i < 4; i++) va[i] = p[i];
            } else {
                const int kk = kg - DD + kh;
                const float4* hp = (const float4*)(A0      + (size_t)grow * DD + kk);
                const float4* mp = (const float4*)(d_gmean + (size_t)g3   * DD + kk);
                const float4* ip = (const float4*)(d_ginv  + (size_t)g3   * DD + kk);
                #pragma unroll
                for (int i = 0; i < 4; i++) {
                    float4 h4 = hp[i], m4 = mp[i], i4 = ip[i];
                    va[i].x = (h4.x - m4.x) * i4.x;
                    va[i].y = (h4.y - m4.y) * i4.y;
                    va[i].z = (h4.z - m4.z) * i4.z;
                    va[i].w = (h4.w - m4.w) * i4.w;
                }
            }
        }
    };

    float4 va[4];
    loadA(0, va);
    cpB(0, 0);

    for (int c = 0; c < NCHUNK; c++) {
        const int s = c & 1;
        // store prefetched A into stage s (safe: stage s last consumed at c-2,
        // released by the __syncthreads of iteration c-1)
        {
            uint32_t* As = AsB + s * STG;
            const float* vf = (const float*)va;
            #pragma unroll
            for (int ii = 0; ii < 16; ii++)
                As[(kh + ii) * KST + prow] = __float_as_uint(vf[ii]);
        }
        asm volatile("cp.async.wait_group 0;" ::: "memory");   // B(c) landed
        __syncthreads();   // everyone done MMA(c-1); As/Bs stage s visible
        if (c + 1 < NCHUNK) {
            loadA(c + 1, va);        // global loads land during MMA(c)
            cpB(c + 1, 1 - s);       // stage 1-s free after the sync above
        }
        // ---- MMA on stage s: 4 k-steps of m16n8k8 ----
        const uint32_t* As = AsB + s * STG;
        const uint32_t* Bs = BsB + s * STG;
        #pragma unroll
        for (int ks = 0; ks < 4; ks++) {
            const int k0 = ks * 8;
            uint32_t af[2][4];
            {
                const uint32_t* a0 = &As[(k0 + lc) * KST + warp_m * 32 + lr];
                const uint32_t* a4 = a0 + 4 * KST;
                #pragma unroll
                for (int i = 0; i < 2; i++) {
                    af[i][0] = a0[i * 16];
                    af[i][1] = a0[i * 16 + 8];
                    af[i][2] = a4[i * 16];
                    af[i][3] = a4[i * 16 + 8];
                }
            }
            const uint32_t* b0 = &Bs[(k0 + lc) * KST + warp_n * 64 + lr];
            const uint32_t* b4 = b0 + 4 * KST;
            #pragma unroll
            for (int j = 0; j < 8; j++) {
                uint32_t bf[2] = { b0[j * 8], b4[j * 8] };
                mma8(acc[0][j], af[0], bf);
                mma8(acc[1][j], af[1], bf);
            }
        }
    }
    __syncthreads();

    // ---- epilogue ----
    if (MODE == 1 || MODE == 3) {
        float* outp = (MODE == 1) ? d_x1 : d_y;
        float* gcs = (MODE == 1) ? d_cs1 : d_cs2;
        float* gcq = (MODE == 1) ? d_cq1 : d_cq2;
        float cs[8][2], cq[8][2];
        #pragma unroll
        for (int j = 0; j < 8; j++)
            #pragma unroll
            for (int e = 0; e < 2; e++) { cs[j][e] = 0.f; cq[j][e] = 0.f; }
        #pragma unroll
        for (int i = 0; i < 2; i++) {
            #pragma unroll
            for (int hh = 0; hh < 2; hh++) {
                int row = row0 + warp_m * 32 + i * 16 + lr + hh * 8;
                float* op = outp + (size_t)row * DD;
                #pragma unroll
                for (int j = 0; j < 8; j++) {
                    int col = warp_n * 64 + j * 8 + lc * 2;
                    float v0 = acc[i][j][hh * 2 + 0] + sbias[col];
                    float v1 = acc[i][j][hh * 2 + 1] + sbias[col + 1];
                    *(float2*)(op + col) = make_float2(v0, v1);
                    cs[j][0] += v0; cq[j][0] += v0 * v0;
                    cs[j][1] += v1; cq[j][1] += v1 * v1;
                }
            }
        }
        #pragma unroll
        for (int o = 4; o < 32; o <<= 1) {
            #pragma unroll
            for (int j = 0; j < 8; j++)
                #pragma unroll
                for (int e = 0; e < 2; e++) {
                    cs[j][e] += __shfl_xor_sync(0xffffffffu, cs[j][e], o);
                    cq[j][e] += __shfl_xor_sync(0xffffffffu, cq[j][e], o);
                }
        }
        if (lr == 0) {
            #pragma unroll
            for (int j = 0; j < 8; j++) {
                int col = warp_n * 64 + j * 8 + lc * 2;
                atomicAdd(&gcs[col],     cs[j][0]);
                atomicAdd(&gcs[col + 1], cs[j][1]);
                atomicAdd(&gcq[col],     cq[j][0]);
                atomicAdd(&gcq[col + 1], cq[j][1]);
            }
        }
    } else {  // MODE 2: gate sigmoid -> h_fused
        #pragma unroll
        for (int i = 0; i < 2; i++) {
            #pragma unroll
            for (int hh = 0; hh < 2; hh++) {
                int row = row0 + warp_m * 32 + i * 16 + lr + hh * 8;
                const float* hp = A0   + (size_t)row * DD;
                const float* xp = d_x1 + (size_t)row * DD;
                float* op = d_hf + (size_t)row * DD;
                #pragma unroll
                for (int j = 0; j < 8; j++) {
                    int col = warp_n * 64 + j * 8 + lc * 2;
                    float2 h2 = *(const float2*)(hp + col);
                    float2 x2 = *(const float2*)(xp + col);
                    float se0 = fmaxf(sa1[col]   * x2.x + sc1[col],   0.f);
                    float se1 = fmaxf(sa1[col+1] * x2.y + sc1[col+1], 0.f);
                    float a0v = acc[i][j][hh * 2 + 0] + sbias[col];
                    float a1v = acc[i][j][hh * 2 + 1] + sbias[col + 1];
                    float g0 = 1.f / (1.f + expf(-a0v));
                    float g1 = 1.f / (1.f + expf(-a1v));
                    *(float2*)(op + col) =
                        make_float2(h2.x + g0 * se0, h2.y + g1 * se1);
                }
            }
        }
    }

    // ---- fused per-graph sum/sumsq of h (MODE 1 only, sorted segments) ----
    if (MODE == 1) {
        if (t < 128) sbt[t] = batch[row0 + t];
        __syncthreads();
        const int d = t & 127, half = t >> 7;
        const int base = half * 64;
        float s = 0.f, q = 0.f, cn = 0.f;
        int cur = sbt[base];
        for (int i = 0; i < 64; i++) {
            int g = sbt[base + i];
            if (g != cur) {
                atomicAdd(&d_gsum[cur * DD + d], s);
                atomicAdd(&d_gsq [cur * DD + d], q);
                if (d == 0) atomicAdd(&d_cnt[cur], cn);
                s = 0.f; q = 0.f; cn = 0.f; cur = g;
            }
            float v = hs[(size_t)(row0 + base + i) * DD + d];
            s += v; q += v * v; cn += 1.f;
        }
        atomicAdd(&d_gsum[cur * DD + d], s);
        atomicAdd(&d_gsq [cur * DD + d], q);
        if (d == 0) atomicAdd(&d_cnt[cur], cn);
    }
}

// ---------------- finalize BN1 + graph mean/inv-std -------------------------
__global__ void finalize1(const float* __restrict__ g1, const float* __restrict__ be1)
{
    int g = blockIdx.x, d = threadIdx.x;
    float cnt = fmaxf(d_cnt[g], 1.f);
    float m  = d_gsum[g * DD + d] / cnt;
    float sq = d_gsq [g * DD + d] / cnt;
    float sd = sqrtf(fmaxf(sq - m * m, 1e-8f));
    d_gmean[g * DD + d] = m;
    d_ginv [g * DD + d] = 1.f / (sd + 1e-8f);
    if (g == 0) {
        float mean = d_cs1[d] / (float)NR;
        float var  = d_cq1[d] / (float)NR - mean * mean;
        float a = g1[d] * rsqrtf(var + 1e-5f);
        d_a1[d] = a;
        d_c1[d] = be1[d] - mean * a;
    }
}

__global__ void finalize2(const float* __restrict__ g2, const float* __restrict__ be2)
{
    int d = threadIdx.x;
    float mean = d_cs2[d] / (float)NR;
    float var  = d_cq2[d] / (float)NR - mean * mean;
    float a = g2[d] * rsqrtf(var + 1e-5f);
    d_a2[d] = a;
    d_c2[d] = be2[d] - mean * a;
}

// ---------------- score logit: warp per row ---------------------------------
__global__ void logit_k(const float* __restrict__ Ws2, const float* __restrict__ bs2,
                        const int* __restrict__ batch)
{
    int w = threadIdx.x >> 5, l = threadIdx.x & 31;
    int row = blockIdx.x * 8 + w;
    float p = 0.f;
    #pragma unroll
    for (int c = 0; c < 4; c++) {
        int col = c * 32 + l;
        float z = fmaxf(d_a2[col] * d_y[(size_t)row * DD + col] + d_c2[col], 0.f);
        p = fmaf(z, Ws2[col], p);
    }
    #pragma unroll
    for (int o = 16; o; o >>= 1) p += __shfl_down_sync(0xffffffffu, p, o);
    if (l == 0) {
        float lg = p + bs2[0];
        d_logit[row] = lg;
        atomicMax(&d_smax[batch[row]], f2o(lg));
    }
}

// ---------------- exp + segment denom ---------------------------------------
__global__ void exp_k(const int* __restrict__ batch)
{
    int r = blockIdx.x * 256 + threadIdx.x;
    if (r >= NR) return;
    int g = batch[r];
    float mx = o2f(d_smax[g]);
    float e = expf(d_logit[r] - mx);
    d_e[r] = e;
    atomicAdd(&d_denom[g], e);
}

// ---------------- weighted segment sum of h_fused * score -------------------
__global__ void wsum_k(const int* __restrict__ batch)
{
    __shared__ int   sb[256];
    __shared__ float ss[256];
    int d = threadIdx.x;
    int r0 = blockIdx.x * 256;
    for (int i = d; i < 256; i += 128) {
        int r = r0 + i;
        if (r < NR) {
            int g = batch[r];
            sb[i] = g;
            ss[i] = d_e[r] / d_denom[g];
        } else sb[i] = -1;
    }
    __syncthreads();
    float a = 0.f;
    int cur = sb[0];
    for (int i = 0; i < 256; i++) {
        int g = sb[i];
        if (g < 0) break;
        if (g != cur) {
            atomicAdd(&d_accb[cur * DD + d], a);
            a = 0.f; cur = g;
        }
        a = fmaf(d_hf[(size_t)(r0 + i) * DD + d], ss[i], a);
    }
    atomicAdd(&d_accb[cur * DD + d], a);
}

// ---------------- final mix --------------------------------------------------
__global__ void final_k(const float* __restrict__ mix, float* __restrict__ out)
{
    int g = blockIdx.x, d = threadIdx.x;
    float alpha = 1.f / (1.f + expf(-mix[0]));
    out[g * DD + d] = alpha * d_accb[g * DD + d] + (1.f - alpha) * d_gmean[g * DD + d];
}

// ---------------- launch ------------------------------------------------------
extern "C" void kernel_launch(void* const* d_in, const int* in_sizes, int n_in,
                              void* d_out, int out_size)
{
    const float* h     = (const float*)d_in[0];
    const float* sub   = (const float*)d_in[1];
    const int*   batch = (const int*)  d_in[2];
    const float* W1    = (const float*)d_in[3];
    const float* b1    = (const float*)d_in[4];
    const float* g1    = (const float*)d_in[5];
    const float* be1   = (const float*)d_in[6];
    const float* Wg    = (const float*)d_in[7];
    const float* bg    = (const float*)d_in[8];
    const float* Ws1   = (const float*)d_in[9];
    const float* bs1   = (const float*)d_in[10];
    const float* g2    = (const float*)d_in[11];
    const float* be2   = (const float*)d_in[12];
    const float* Ws2   = (const float*)d_in[13];
    const float* bs2   = (const float*)d_in[14];
    const float* mix   = (const float*)d_in[15];
    float* out = (float*)d_out;

    static int attr_done = 0;
    if (!attr_done) {
        cudaFuncSetAttribute(mma_gemm<2, 1>,
            cudaFuncAttributeMaxDynamicSharedMemorySize, SMEMSZ);
        cudaFuncSetAttribute(mma_gemm<8, 2>,
            cudaFuncAttributeMaxDynamicSharedMemorySize, SMEMSZ);
        cudaFuncSetAttribute(mma_gemm<8, 3>,
            cudaFuncAttributeMaxDynamicSharedMemorySize, SMEMSZ);
        attr_done = 1;
    }

    init_k<<<GG * DD / 128, 128>>>();
    mma_gemm<2, 1><<<NR / 128, 256, SMEMSZ>>>(sub, W1, b1, batch, h);  // x1 + BN1 + seg stats
    finalize1<<<GG, 128>>>(g1, be1);                                   // BN1 affine + graph stats
    mma_gemm<8, 2><<<NR / 128, 256, SMEMSZ>>>(h, Wg, bg, batch, h);    // gate -> h_fused
    mma_gemm<8, 3><<<NR / 128, 256, SMEMSZ>>>(h, Ws1, bs1, batch, h);  // y + BN2 stats
    finalize2<<<1, 128>>>(g2, be2);                                    // BN2 affine
    logit_k<<<NR / 8, 256>>>(Ws2, bs2, batch);                         // logits + segment max
    exp_k<<<(NR + 255) / 256, 256>>>(batch);                           // exp + segment denom
    wsum_k<<<(NR + 255) / 256, 128>>>(batch);                          // weighted segment sum
    final_k<<<GG, 128>>>(mix, out);                                    // alpha mix
}